// round 1
// baseline (speedup 1.0000x reference)
#include <cuda_runtime.h>
#include <cstdint>

// ---------------- problem constants ----------------
#define C_CORES 64
#define D_EMB   128
#define CD      (C_CORES * D_EMB)   // 8192

// K1 launch geometry: 3 blocks/SM * 148 SMs = 444 blocks, 2 rowgroups each
#define K1_GRID   444
#define RG        2
#define K1_THREADS 256
#define UNROLL    8

// ---------------- scratch (no allocations allowed) ----------------
__device__ float g_partial[(size_t)K1_GRID * CD];   // per-block segmax partials (~14.5 MB)
__device__ int   g_counts [K1_GRID * C_CORES];      // per-block counts
__device__ float g_E[CD];                           // core_embs [64,128]
__device__ float g_T[CD];                           // core_embs @ W_msg [64,128]

__device__ __forceinline__ float neg_inf() { return __int_as_float(0xff800000); }

// ---------------- K1: per-block segment max + counts ----------------
__global__ __launch_bounds__(K1_THREADS, 3)
void k1_segmax(const int* __restrict__ assign,
               const float* __restrict__ emb,
               int Q)
{
    extern __shared__ float sm[];           // RG * 8192 floats = 64 KB
    __shared__ int sc[RG][C_CORES];

    const int tid = threadIdx.x;            // 0..255
    const int rg  = tid >> 7;               // rowgroup 0/1
    const int t   = tid & 127;              // column
    float* my = sm + rg * CD;

    // init
    for (int i = tid; i < RG * CD; i += K1_THREADS) sm[i] = neg_inf();
    if (tid < RG * C_CORES) sc[tid >> 6][tid & 63] = 0;
    __syncthreads();

    const int rgid     = blockIdx.x * RG + rg;
    const int total_rg = K1_GRID * RG;
    const int chunk    = (Q + total_rg - 1) / total_rg;
    const int q0       = rgid * chunk;
    const int q1       = (q0 + chunk < Q) ? (q0 + chunk) : Q;

    for (int q = q0; q < q1; q += UNROLL) {
        int   cr[UNROLL];
        float v [UNROLL];
#pragma unroll
        for (int u = 0; u < UNROLL; u++) {
            int qq = q + u;
            if (qq < q1) {
                cr[u] = assign[qq];                         // warp-uniform broadcast
                v[u]  = emb[(size_t)qq * D_EMB + t];        // coalesced 512B/row
            } else {
                cr[u] = -1;
            }
        }
#pragma unroll
        for (int u = 0; u < UNROLL; u++) {
            if (cr[u] >= 0) {
                float* p = &my[cr[u] * D_EMB + t];          // uniform core -> no bank conflict
                if (v[u] > *p) *p = v[u];
                if (t == 0) sc[rg][cr[u]]++;
            }
        }
    }
    __syncthreads();

    // merge rowgroups, write partials
    const size_t base = (size_t)blockIdx.x * CD;
    for (int i = tid; i < CD; i += K1_THREADS) {
        float m = sm[i];
#pragma unroll
        for (int r = 1; r < RG; r++) m = fmaxf(m, sm[r * CD + i]);
        g_partial[base + i] = m;
    }
    if (tid < C_CORES) {
        int cc = 0;
#pragma unroll
        for (int r = 0; r < RG; r++) cc += sc[r][tid];
        g_counts[blockIdx.x * C_CORES + tid] = cc;
    }
}

// ---------------- K2: reduce partials -> E, then T = E @ W_msg ----------------
__global__ __launch_bounds__(128)
void k2_reduce_msg(const float* __restrict__ padding_emb,
                   const float* __restrict__ W_msg)
{
    const int c = blockIdx.x;     // core
    const int t = threadIdx.x;    // column

    float m = neg_inf();
    int   cnt = 0;
    const float* pp = g_partial + (size_t)c * D_EMB + t;
    const int*   pc = g_counts  + c;
#pragma unroll 4
    for (int p = 0; p < K1_GRID; p++) {
        m   = fmaxf(m, pp[(size_t)p * CD]);
        cnt += pc[p * C_CORES];
    }
    float e = (cnt > 0) ? m : padding_emb[t];
    g_E[c * D_EMB + t] = e;

    __shared__ float sE[D_EMB];
    sE[t] = e;
    __syncthreads();

    // T[c][t] = sum_k E[c][k] * W_msg[k][t]  (4 accumulators to pipeline FMA)
    float a0 = 0.f, a1 = 0.f, a2 = 0.f, a3 = 0.f;
#pragma unroll
    for (int k = 0; k < D_EMB; k += 4) {
        a0 = fmaf(sE[k + 0], W_msg[(k + 0) * D_EMB + t], a0);
        a1 = fmaf(sE[k + 1], W_msg[(k + 1) * D_EMB + t], a1);
        a2 = fmaf(sE[k + 2], W_msg[(k + 2) * D_EMB + t], a2);
        a3 = fmaf(sE[k + 3], W_msg[(k + 3) * D_EMB + t], a3);
    }
    g_T[c * D_EMB + t] = (a0 + a1) + (a2 + a3);
}

// ---------------- K3: out = relu(E@W_self + con@T + b) ----------------
__global__ __launch_bounds__(128)
void k3_epilogue(const float* __restrict__ core_con,
                 const float* __restrict__ W_self,
                 const float* __restrict__ bvec,
                 float* __restrict__ out)
{
    const int c = blockIdx.x;
    const int t = threadIdx.x;

    __shared__ float sE[D_EMB];
    sE[t] = g_E[c * D_EMB + t];
    __syncthreads();

    float a0 = 0.f, a1 = 0.f, a2 = 0.f, a3 = 0.f;
#pragma unroll
    for (int k = 0; k < D_EMB; k += 4) {
        a0 = fmaf(sE[k + 0], W_self[(k + 0) * D_EMB + t], a0);
        a1 = fmaf(sE[k + 1], W_self[(k + 1) * D_EMB + t], a1);
        a2 = fmaf(sE[k + 2], W_self[(k + 2) * D_EMB + t], a2);
        a3 = fmaf(sE[k + 3], W_self[(k + 3) * D_EMB + t], a3);
    }
    float s = bvec[t] + (a0 + a1) + (a2 + a3);

    float m0 = 0.f, m1 = 0.f;
#pragma unroll
    for (int j = 0; j < C_CORES; j += 2) {
        m0 = fmaf(core_con[c * C_CORES + j + 0], g_T[(j + 0) * D_EMB + t], m0);
        m1 = fmaf(core_con[c * C_CORES + j + 1], g_T[(j + 1) * D_EMB + t], m1);
    }
    float r = s + m0 + m1;
    out[c * D_EMB + t] = fmaxf(r, 0.f);
}

// ---------------- launch ----------------
extern "C" void kernel_launch(void* const* d_in, const int* in_sizes, int n_in,
                              void* d_out, int out_size)
{
    const int*   assign      = (const int*)  d_in[0];
    const float* emb         = (const float*)d_in[1];
    const float* padding_emb = (const float*)d_in[2];
    const float* core_con    = (const float*)d_in[3];
    const float* W_self      = (const float*)d_in[4];
    const float* W_msg       = (const float*)d_in[5];
    const float* bvec        = (const float*)d_in[6];
    float* out = (float*)d_out;

    const int Q = in_sizes[0];

    const int smem = RG * CD * (int)sizeof(float);   // 64 KB
    cudaFuncSetAttribute(k1_segmax, cudaFuncAttributeMaxDynamicSharedMemorySize, smem);

    k1_segmax<<<K1_GRID, K1_THREADS, smem>>>(assign, emb, Q);
    k2_reduce_msg<<<C_CORES, D_EMB>>>(padding_emb, W_msg);
    k3_epilogue<<<C_CORES, D_EMB>>>(core_con, W_self, bvec, out);
}

// round 2
// speedup vs baseline: 1.8840x; 1.8840x over previous
#include <cuda_runtime.h>
#include <cstdint>

// ---------------- problem constants ----------------
#define C_CORES 64
#define D_EMB   128
#define CD      (C_CORES * D_EMB)        // 8192 floats = 32 KB per table

// ---------------- K1 geometry ----------------
#define K1_TPB    384                    // 12 warps = 6 warp-pairs = 6 tables
#define TABLES    6
#define UNR       16
#define MAX_BLK   160                    // upper bound on SM count

// ---------------- scratch ----------------
__device__ float              g_partial[(size_t)MAX_BLK * CD];  // per-block merged segmax (~5 MB)
__device__ unsigned long long g_mask[MAX_BLK];                  // per-block "core seen" bitmask
__device__ float              g_E[CD];                          // core_embs  [64,128]
__device__ float              g_T[CD];                          // E @ W_msg  [64,128]

__device__ __forceinline__ float neg_inf() { return __int_as_float(0xff800000); }

// =====================================================================
// K1: streaming segment-max. Each warp-pair owns a private 32 KB table;
// warp A handles cols [0,64), warp B cols [64,128) -> race-free, no sync.
// =====================================================================
__global__ __launch_bounds__(K1_TPB, 1)
void k1_segmax(const int* __restrict__ assign,
               const float* __restrict__ emb,
               int Q)
{
    extern __shared__ float sm[];            // TABLES * 8192 floats = 192 KB
    __shared__ unsigned char s_seen[C_CORES];

    const int tid  = threadIdx.x;
    const int wid  = tid >> 5;
    const int lane = tid & 31;
    const int tbl  = wid >> 1;               // table id 0..5
    const int half = wid & 1;                // column half 0/1
    float* my = sm + tbl * CD;

    // init tables to -inf (vectorized)
    {
        float4 ninf4 = make_float4(neg_inf(), neg_inf(), neg_inf(), neg_inf());
        float4* s4 = (float4*)sm;
        for (int i = tid; i < TABLES * CD / 4; i += K1_TPB) s4[i] = ninf4;
        if (tid < C_CORES) s_seen[tid] = 0;
    }
    __syncthreads();

    // contiguous qubit chunk per warp-pair (rowgroup)
    const int n_rg  = gridDim.x * TABLES;
    const int rgid  = blockIdx.x * TABLES + tbl;
    const int chunk = (Q + n_rg - 1) / n_rg;
    const int q0    = rgid * chunk;
    const int q1    = (q0 + chunk < Q) ? (q0 + chunk) : Q;

    // float2 view: row q starts at emb2 + q*64; this warp covers half*32 + lane
    const float2* emb2 = (const float2*)emb;
    const int col2 = half * 32 + lane;                 // float2 column index 0..63
    float* myp = my + half * 64 + lane * 2;            // byte-equiv of col within a core row

    int q = q0;
    for (; q + UNR <= q1; q += UNR) {
        int    cr[UNR];
        float2 v [UNR];
#pragma unroll
        for (int u = 0; u < UNR; u++) {
            cr[u] = __ldg(assign + q + u);                         // warp-uniform
            v[u]  = __ldg(emb2 + (size_t)(q + u) * 64 + col2);     // 256B/warp coalesced
        }
#pragma unroll
        for (int u = 0; u < UNR; u++) {
            float2* p = (float2*)(myp + cr[u] * D_EMB);
            float2 o = *p;
            o.x = fmaxf(o.x, v[u].x);
            o.y = fmaxf(o.y, v[u].y);
            *p = o;
            if (lane == 0 && half == 0) s_seen[cr[u]] = 1;
        }
    }
    for (; q < q1; q++) {                                          // tail
        int c = __ldg(assign + q);
        float2 v = __ldg(emb2 + (size_t)q * 64 + col2);
        float2* p = (float2*)(myp + c * D_EMB);
        float2 o = *p;
        o.x = fmaxf(o.x, v.x);
        o.y = fmaxf(o.y, v.y);
        *p = o;
        if (lane == 0 && half == 0) s_seen[c] = 1;
    }
    __syncthreads();

    // merge the 6 tables -> one partial per block (float4)
    {
        const float4* s4 = (const float4*)sm;
        float4* g4 = (float4*)(g_partial + (size_t)blockIdx.x * CD);
        for (int i = tid; i < CD / 4; i += K1_TPB) {
            float4 m = s4[i];
#pragma unroll
            for (int r = 1; r < TABLES; r++) {
                float4 o = s4[r * (CD / 4) + i];
                m.x = fmaxf(m.x, o.x); m.y = fmaxf(m.y, o.y);
                m.z = fmaxf(m.z, o.z); m.w = fmaxf(m.w, o.w);
            }
            g4[i] = m;
        }
    }
    // pack seen-flags into a 64-bit mask (warp 0)
    if (wid == 0) {
        unsigned b0 = __ballot_sync(0xffffffffu, s_seen[lane]      != 0);
        unsigned b1 = __ballot_sync(0xffffffffu, s_seen[lane + 32] != 0);
        if (lane == 0)
            g_mask[blockIdx.x] = ((unsigned long long)b1 << 32) | (unsigned long long)b0;
    }
}

// =====================================================================
// K2: reduce partials -> E (with padding), then T = E @ W_msg.
// 512 threads: 4-way split over the partial dimension, then over K.
// =====================================================================
__global__ __launch_bounds__(512)
void k2_reduce_msg(const float* __restrict__ padding_emb,
                   const float* __restrict__ W_msg,
                   int nparts)
{
    __shared__ float              sred[4][D_EMB];
    __shared__ unsigned long long smask[4];
    __shared__ float              sE[D_EMB];

    const int c   = blockIdx.x;
    const int tid = threadIdx.x;
    const int t   = tid & 127;
    const int s   = tid >> 7;

    float m = neg_inf();
    unsigned long long mk = 0ull;
    const float* pp = g_partial + (size_t)c * D_EMB + t;
#pragma unroll 8
    for (int p = s; p < nparts; p += 4) {
        m  = fmaxf(m, pp[(size_t)p * CD]);
        mk |= g_mask[p];
    }
    sred[s][t] = m;
    if (t == 0) smask[s] = mk;
    __syncthreads();

    if (s == 0) {
        float mm = fmaxf(fmaxf(sred[0][t], sred[1][t]), fmaxf(sred[2][t], sred[3][t]));
        unsigned long long allm = smask[0] | smask[1] | smask[2] | smask[3];
        float e = ((allm >> c) & 1ull) ? mm : padding_emb[t];
        g_E[c * D_EMB + t] = e;
        sE[t] = e;
    }
    __syncthreads();

    // T[c][t] = sum_k sE[k] * W_msg[k][t], K split 4 ways
    float a0 = 0.f, a1 = 0.f;
#pragma unroll
    for (int k = s * 32; k < s * 32 + 32; k += 2) {
        a0 = fmaf(sE[k + 0], W_msg[(k + 0) * D_EMB + t], a0);
        a1 = fmaf(sE[k + 1], W_msg[(k + 1) * D_EMB + t], a1);
    }
    __syncthreads();
    sred[s][t] = a0 + a1;
    __syncthreads();
    if (s == 0)
        g_T[c * D_EMB + t] = (sred[0][t] + sred[1][t]) + (sred[2][t] + sred[3][t]);
}

// =====================================================================
// K3: out = relu(E @ W_self + con @ T + b), 4-way K split
// =====================================================================
__global__ __launch_bounds__(512)
void k3_epilogue(const float* __restrict__ core_con,
                 const float* __restrict__ W_self,
                 const float* __restrict__ bvec,
                 float* __restrict__ out)
{
    __shared__ float sE[D_EMB];
    __shared__ float part[4][D_EMB];

    const int c   = blockIdx.x;
    const int tid = threadIdx.x;
    const int t   = tid & 127;
    const int s   = tid >> 7;

    if (s == 0) sE[t] = g_E[c * D_EMB + t];
    __syncthreads();

    float a0 = 0.f, a1 = 0.f;
#pragma unroll
    for (int k = s * 32; k < s * 32 + 32; k += 2) {
        a0 = fmaf(sE[k + 0], W_self[(k + 0) * D_EMB + t], a0);
        a1 = fmaf(sE[k + 1], W_self[(k + 1) * D_EMB + t], a1);
    }
#pragma unroll
    for (int j = s * 16; j < s * 16 + 16; j++) {
        a0 = fmaf(core_con[c * C_CORES + j], g_T[j * D_EMB + t], a0);
    }
    part[s][t] = a0 + a1;
    __syncthreads();
    if (s == 0) {
        float r = (part[0][t] + part[1][t]) + (part[2][t] + part[3][t]) + bvec[t];
        out[c * D_EMB + t] = fmaxf(r, 0.f);
    }
}

// ---------------- launch ----------------
extern "C" void kernel_launch(void* const* d_in, const int* in_sizes, int n_in,
                              void* d_out, int out_size)
{
    const int*   assign      = (const int*)  d_in[0];
    const float* emb         = (const float*)d_in[1];
    const float* padding_emb = (const float*)d_in[2];
    const float* core_con    = (const float*)d_in[3];
    const float* W_self      = (const float*)d_in[4];
    const float* W_msg       = (const float*)d_in[5];
    const float* bvec        = (const float*)d_in[6];
    float* out = (float*)d_out;

    const int Q = in_sizes[0];

    int nsm = 148;
    cudaDeviceGetAttribute(&nsm, cudaDevAttrMultiProcessorCount, 0);
    if (nsm > MAX_BLK) nsm = MAX_BLK;

    const int smem = TABLES * CD * (int)sizeof(float);   // 192 KB
    static bool attr_set = false;
    cudaFuncSetAttribute(k1_segmax, cudaFuncAttributeMaxDynamicSharedMemorySize, smem);
    (void)attr_set;

    k1_segmax<<<nsm, K1_TPB, smem>>>(assign, emb, Q);
    k2_reduce_msg<<<C_CORES, 512>>>(padding_emb, W_msg, nsm);
    k3_epilogue<<<C_CORES, 512>>>(core_con, W_self, bvec, out);
}

// round 3
// speedup vs baseline: 1.8946x; 1.0056x over previous
#include <cuda_runtime.h>
#include <cstdint>

// ---------------- problem constants ----------------
#define C_CORES 64
#define D_EMB   128
#define CD      (C_CORES * D_EMB)        // 8192 floats = 32 KB per table

// ---------------- K1 geometry ----------------
#define K1_TPB    768                    // 24 warps = 6 tables x 4 warps
#define TABLES    6
#define WPT       4                      // warps per table (column split)
#define UNR       16

// ---------------- global scratch ----------------
__device__ unsigned int g_tab[CD];       // encoded segment-max table
__device__ unsigned int g_mask32[2];     // "core seen" bitmask

// order-preserving float <-> uint encoding (no NaNs in data)
__device__ __forceinline__ unsigned int enc(float f) {
    unsigned int u = __float_as_uint(f);
    return (u & 0x80000000u) ? ~u : (u | 0x80000000u);
}
__device__ __forceinline__ float dec(unsigned int u) {
    u = (u & 0x80000000u) ? (u & 0x7fffffffu) : ~u;
    return __uint_as_float(u);
}
__device__ __forceinline__ float neg_inf() { return __int_as_float(0xff800000); }

// =====================================================================
// K0: zero the global table + mask (encoded domain: 0 < any real value)
// =====================================================================
__global__ void k0_init()
{
    int i = blockIdx.x * blockDim.x + threadIdx.x;
    if (i < CD) g_tab[i] = 0u;
    if (i < 2)  g_mask32[i] = 0u;
}

// =====================================================================
// K1: streaming segment-max. 6 private 32 KB tables per block, 4 warps
// per table (each warp owns 32 disjoint columns -> race-free, no sync).
// Block tail merges tables and REDG.MAX's into the global encoded table.
// =====================================================================
__global__ __launch_bounds__(K1_TPB, 1)
void k1_segmax(const int* __restrict__ assign,
               const float* __restrict__ emb,
               int Q)
{
    extern __shared__ float sm[];            // TABLES * 8192 floats = 192 KB
    __shared__ unsigned char s_seen[C_CORES];

    const int tid  = threadIdx.x;
    const int wid  = tid >> 5;
    const int lane = tid & 31;
    const int tbl  = wid >> 2;               // table 0..5
    const int sub  = wid & 3;                // column quarter 0..3
    const int col  = sub * 32 + lane;        // owned float column 0..127
    float* my = sm + tbl * CD + col;

    // init tables to -inf
    {
        float4 ninf4 = make_float4(neg_inf(), neg_inf(), neg_inf(), neg_inf());
        float4* s4 = (float4*)sm;
        for (int i = tid; i < TABLES * CD / 4; i += K1_TPB) s4[i] = ninf4;
        if (tid < C_CORES) s_seen[tid] = 0;
    }
    __syncthreads();

    // contiguous qubit chunk per table-group
    const int n_rg  = gridDim.x * TABLES;
    const int rgid  = blockIdx.x * TABLES + tbl;
    const int chunk = (Q + n_rg - 1) / n_rg;
    const int q0    = rgid * chunk;
    const int q1    = (q0 + chunk < Q) ? (q0 + chunk) : Q;

    int q = q0;
    for (; q + UNR <= q1; q += UNR) {
        int   cr[UNR];
        float v [UNR];
#pragma unroll
        for (int u = 0; u < UNR; u++) {
            cr[u] = __ldg(assign + q + u);                       // warp-uniform (L1 shared)
            v[u]  = __ldg(emb + (size_t)(q + u) * D_EMB + col);  // 128B/warp coalesced
        }
#pragma unroll
        for (int u = 0; u < UNR; u++) {
            float* p = my + cr[u] * D_EMB;
            float o = *p;
            if (v[u] > o) *p = v[u];
            if (lane == 0 && sub == 0) s_seen[cr[u]] = 1;
        }
    }
    for (; q < q1; q++) {                                        // tail
        int c = __ldg(assign + q);
        float v = __ldg(emb + (size_t)q * D_EMB + col);
        float* p = my + c * D_EMB;
        if (v > *p) *p = v;
        if (lane == 0 && sub == 0) s_seen[c] = 1;
    }
    __syncthreads();

    // merge 6 tables, encode, fold into global table via no-return atomicMax
    for (int i = tid; i < CD; i += K1_TPB) {
        float m = sm[i];
#pragma unroll
        for (int r = 1; r < TABLES; r++) m = fmaxf(m, sm[r * CD + i]);
        atomicMax(&g_tab[i], enc(m));
    }
    if (wid == 0) {
        unsigned b0 = __ballot_sync(0xffffffffu, s_seen[lane]      != 0);
        unsigned b1 = __ballot_sync(0xffffffffu, s_seen[lane + 32] != 0);
        if (lane == 0) {
            if (b0) atomicOr(&g_mask32[0], b0);
            if (b1) atomicOr(&g_mask32[1], b1);
        }
    }
}

// =====================================================================
// Epilogue: out = relu(E@W_self + (con@E)@W_msg + b)
// (associativity: con @ (E @ W_msg) == (con @ E) @ W_msg)
// One block per core, 128 threads.
// =====================================================================
__global__ __launch_bounds__(128)
void k_epilogue(const float* __restrict__ padding_emb,
                const float* __restrict__ core_con,
                const float* __restrict__ W_self,
                const float* __restrict__ W_msg,
                const float* __restrict__ bvec,
                float* __restrict__ out)
{
    __shared__ float sE[C_CORES][D_EMB];   // 32 KB
    __shared__ float sM[D_EMB];

    const int c = blockIdx.x;
    const int t = threadIdx.x;

    // decode global table -> E (with padding for empty cores)
    unsigned m0 = g_mask32[0], m1 = g_mask32[1];
    unsigned long long mask = ((unsigned long long)m1 << 32) | m0;
    float pad = padding_emb[t];
    for (int j = 0; j < C_CORES; j++) {
        unsigned int u = g_tab[j * D_EMB + t];
        float e = dec(u);
        sE[j][t] = ((mask >> j) & 1ull) ? e : pad;
    }
    __syncthreads();

    // Msum[t] = sum_j con[c,j] * E[j,t]
    {
        float a0 = 0.f, a1 = 0.f;
#pragma unroll
        for (int j = 0; j < C_CORES; j += 2) {
            a0 = fmaf(core_con[c * C_CORES + j + 0], sE[j + 0][t], a0);
            a1 = fmaf(core_con[c * C_CORES + j + 1], sE[j + 1][t], a1);
        }
        sM[t] = a0 + a1;
    }
    __syncthreads();

    // out[c,t] = relu(b[t] + sum_k E[c,k]*W_self[k,t] + sum_k Msum[k]*W_msg[k,t])
    float a0 = 0.f, a1 = 0.f, a2 = 0.f, a3 = 0.f;
#pragma unroll 4
    for (int k = 0; k < D_EMB; k += 2) {
        a0 = fmaf(sE[c][k + 0], W_self[(k + 0) * D_EMB + t], a0);
        a1 = fmaf(sM[k + 0],    W_msg [(k + 0) * D_EMB + t], a1);
        a2 = fmaf(sE[c][k + 1], W_self[(k + 1) * D_EMB + t], a2);
        a3 = fmaf(sM[k + 1],    W_msg [(k + 1) * D_EMB + t], a3);
    }
    float r = bvec[t] + (a0 + a2) + (a1 + a3);
    out[c * D_EMB + t] = fmaxf(r, 0.f);
}

// ---------------- launch ----------------
extern "C" void kernel_launch(void* const* d_in, const int* in_sizes, int n_in,
                              void* d_out, int out_size)
{
    const int*   assign      = (const int*)  d_in[0];
    const float* emb         = (const float*)d_in[1];
    const float* padding_emb = (const float*)d_in[2];
    const float* core_con    = (const float*)d_in[3];
    const float* W_self      = (const float*)d_in[4];
    const float* W_msg       = (const float*)d_in[5];
    const float* bvec        = (const float*)d_in[6];
    float* out = (float*)d_out;

    const int Q = in_sizes[0];

    int nsm = 148;
    cudaDeviceGetAttribute(&nsm, cudaDevAttrMultiProcessorCount, 0);

    const int smem = TABLES * CD * (int)sizeof(float);   // 192 KB
    cudaFuncSetAttribute(k1_segmax, cudaFuncAttributeMaxDynamicSharedMemorySize, smem);

    k0_init<<<(CD + 1023) / 1024, 1024>>>();
    k1_segmax<<<nsm, K1_TPB, smem>>>(assign, emb, Q);
    k_epilogue<<<C_CORES, D_EMB>>>(padding_emb, core_con, W_self, W_msg, bvec, out);
}